// round 10
// baseline (speedup 1.0000x reference)
#include <cuda_runtime.h>
#include <cstdint>
#include <math.h>

// Problem constants
#define EDIM 512
#define NSEQ 4096
#define NHEAD 8
#define HDIM 2048

typedef unsigned long long u64;

// ---- tf32 mma.sync helpers (family-agnostic PTX, works on compute_103) ----
__device__ __forceinline__ uint32_t tf32r(float f) {
    uint32_t u;
    asm("cvt.rna.tf32.f32 %0, %1;" : "=r"(u) : "f"(f));
    return u;
}
__device__ __forceinline__ float tf32rf(float f) {
    return __uint_as_float(tf32r(f));
}
__device__ __forceinline__ void mma1688(float* c, const uint32_t* a, const uint32_t* b) {
    asm volatile(
        "mma.sync.aligned.m16n8k8.row.col.f32.tf32.tf32.f32 "
        "{%0,%1,%2,%3}, {%4,%5,%6,%7}, {%8,%9}, {%0,%1,%2,%3};"
        : "+f"(c[0]), "+f"(c[1]), "+f"(c[2]), "+f"(c[3])
        : "r"(a[0]), "r"(a[1]), "r"(a[2]), "r"(a[3]), "r"(b[0]), "r"(b[1]));
}
__device__ __forceinline__ uint32_t smem_u32(const void* p) {
    uint32_t a;
    asm("{ .reg .u64 t; cvta.to.shared.u64 t, %1; cvt.u32.u64 %0, t; }" : "=r"(a) : "l"(p));
    return a;
}
__device__ __forceinline__ void cpa16(uint32_t s, const void* g) {
    asm volatile("cp.async.cg.shared.global [%0], [%1], 16;" :: "r"(s), "l"(g));
}
#define CP_COMMIT() asm volatile("cp.async.commit_group;" ::: "memory")
#define CP_WAIT0()  asm volatile("cp.async.wait_group 0;" ::: "memory")
#define CP_WAIT1()  asm volatile("cp.async.wait_group 1;" ::: "memory")

// Scratch (alloc-free rule: __device__ globals)
__device__ float g_h1[NSEQ * EDIM];
__device__ float g_qkv[NSEQ * 3 * EDIM];
__device__ float g_attn[NSEQ * EDIM];
__device__ float g_x1[NSEQ * EDIM];
__device__ float g_h2[NSEQ * EDIM];
__device__ float g_m1[NSEQ * HDIM];
__device__ float g_m2[NSEQ * HDIM];
// tf32-pre-rounded weights
__device__ float g_wqkv[3 * EDIM * EDIM];
__device__ float g_wproj[EDIM * EDIM];
__device__ float g_w1[HDIM * EDIM];
__device__ float g_w2[HDIM * HDIM];
__device__ float g_w3[EDIM * HDIM];

// ===========================================================================
// Weight pre-rounding (fp32 -> tf32-exact fp32), float4 grid-stride
// ===========================================================================
__global__ void round_w_kernel(const float* __restrict__ src, float* __restrict__ dst,
                               int n4) {
    int i = blockIdx.x * blockDim.x + threadIdx.x;
    if (i < n4) {
        float4 v = ((const float4*)src)[i];
        v.x = tf32rf(v.x); v.y = tf32rf(v.y); v.z = tf32rf(v.z); v.w = tf32rf(v.w);
        ((float4*)dst)[i] = v;
    }
}

// ===========================================================================
// LayerNorm (output rounded to tf32-exact fp32; feeds GEMM A only)
// ===========================================================================
__global__ void ln_kernel(const float* __restrict__ X, const float* __restrict__ g,
                          const float* __restrict__ b, float* __restrict__ Y) {
    const int row = blockIdx.x;
    const int t = threadIdx.x;  // 128 threads
    const float4* Xv = (const float4*)(X + (size_t)row * EDIM);
    float4 v = Xv[t];

    __shared__ float red[4];
    float s = v.x + v.y + v.z + v.w;
    #pragma unroll
    for (int o = 16; o > 0; o >>= 1) s += __shfl_down_sync(0xffffffffu, s, o);
    if ((t & 31) == 0) red[t >> 5] = s;
    __syncthreads();
    float mean = (red[0] + red[1] + red[2] + red[3]) * (1.0f / EDIM);
    __syncthreads();

    float dx = v.x - mean, dy = v.y - mean, dz = v.z - mean, dw = v.w - mean;
    float s2 = dx * dx + dy * dy + dz * dz + dw * dw;
    #pragma unroll
    for (int o = 16; o > 0; o >>= 1) s2 += __shfl_down_sync(0xffffffffu, s2, o);
    if ((t & 31) == 0) red[t >> 5] = s2;
    __syncthreads();
    float var = (red[0] + red[1] + red[2] + red[3]) * (1.0f / EDIM);
    float rs = rsqrtf(var + 1e-5f);

    float4 gv = ((const float4*)g)[t];
    float4 bv = ((const float4*)b)[t];
    float4 o4;
    o4.x = tf32rf(dx * rs * gv.x + bv.x);
    o4.y = tf32rf(dy * rs * gv.y + bv.y);
    o4.z = tf32rf(dz * rs * gv.z + bv.z);
    o4.w = tf32rf(dw * rs * gv.w + bv.w);
    ((float4*)(Y + (size_t)row * EDIM))[t] = o4;
}

// ===========================================================================
// tf32 mma.sync GEMM: C[M,N] = A[M,K]*B[N,K]^T (+bias, +res, +relu, +round)
// CTA 128x128, 8 warps (2x4), warp tile 64x32, K-chunk 16.
// 3-stage cp.async pipeline, dynamic smem. Inputs are tf32-exact fp32, so the
// raw-bit feed into the tf32 MMA is exact (RNA applied at producers).
// ===========================================================================
#define SMS 20                 // smem row stride (uint32)
#define G_STAGE (128 * SMS)    // uint32 per matrix per stage
#define G_SMEM_BYTES (3 * 2 * G_STAGE * 4)   // 61440

template <bool RELU, bool RES, bool ROUND>
__global__ void __launch_bounds__(256, 2)
mma_gemm(const float* __restrict__ A, const float* __restrict__ B,
         const float* __restrict__ bias, const float* __restrict__ Rs,
         float* __restrict__ C, int M, int N, int K) {
    extern __shared__ uint32_t dsm[];
    uint32_t* sA = dsm;                    // 3 stages x 128*SMS
    uint32_t* sB = dsm + 3 * G_STAGE;      // 3 stages x 128*SMS

    const int t = threadIdx.x;
    const int wid = t >> 5;
    const int lid = t & 31;
    const int mBase = blockIdx.y * 128;
    const int nBase = blockIdx.x * 128;

    const int wm = (wid >> 2) * 64;
    const int wn = (wid & 3) * 32;
    const int g = lid >> 2;
    const int t4 = lid & 3;

    float acc[4][4][4];
    #pragma unroll
    for (int mi = 0; mi < 4; mi++)
        #pragma unroll
        for (int ni = 0; ni < 4; ni++)
            #pragma unroll
            for (int r = 0; r < 4; r++) acc[mi][ni][r] = 0.0f;

    const int s0 = t * 2;
    const int lrow0 = s0 >> 2, lq0 = (s0 & 3) * 4;
    const int lrow1 = (s0 + 1) >> 2, lq1 = ((s0 + 1) & 3) * 4;

    const float* Ap0 = A + (size_t)(mBase + lrow0) * K + lq0;
    const float* Ap1 = A + (size_t)(mBase + lrow1) * K + lq1;
    const float* Bp0 = B + (size_t)(nBase + lrow0) * K + lq0;
    const float* Bp1 = B + (size_t)(nBase + lrow1) * K + lq1;
    uint32_t sa0[3], sa1[3], sb0[3], sb1[3];
    #pragma unroll
    for (int st = 0; st < 3; st++) {
        sa0[st] = smem_u32(&sA[st * G_STAGE + lrow0 * SMS + lq0]);
        sa1[st] = smem_u32(&sA[st * G_STAGE + lrow1 * SMS + lq1]);
        sb0[st] = smem_u32(&sB[st * G_STAGE + lrow0 * SMS + lq0]);
        sb1[st] = smem_u32(&sB[st * G_STAGE + lrow1 * SMS + lq1]);
    }

    auto issue_chunk = [&](int c, int st) {
        const int k0 = c << 4;
        cpa16(sa0[st], Ap0 + k0);
        cpa16(sa1[st], Ap1 + k0);
        cpa16(sb0[st], Bp0 + k0);
        cpa16(sb1[st], Bp1 + k0);
    };

    const int T = K >> 4;
    issue_chunk(0, 0); CP_COMMIT();
    if (T > 1) { issue_chunk(1, 1); CP_COMMIT(); }

    int st = 0;
    for (int c = 0; c < T; c++) {
        if (c + 1 < T) CP_WAIT1(); else CP_WAIT0();
        __syncthreads();  // data of chunk c visible to all; all done with buf st (from c-3)
        if (c + 2 < T) { issue_chunk(c + 2, (st + 2 >= 3) ? st - 1 : st + 2); CP_COMMIT(); }

        const uint32_t* cA = sA + st * G_STAGE;
        const uint32_t* cB = sB + st * G_STAGE;
        #pragma unroll
        for (int ks = 0; ks < 16; ks += 8) {
            uint32_t af[4][4], bf[4][2];
            #pragma unroll
            for (int mi = 0; mi < 4; mi++) {
                int base = (wm + mi * 16 + g) * SMS + ks + t4;
                af[mi][0] = cA[base];
                af[mi][1] = cA[base + 8 * SMS];
                af[mi][2] = cA[base + 4];
                af[mi][3] = cA[base + 8 * SMS + 4];
            }
            #pragma unroll
            for (int ni = 0; ni < 4; ni++) {
                int base = (wn + ni * 8 + g) * SMS + ks + t4;
                bf[ni][0] = cB[base];
                bf[ni][1] = cB[base + 4];
            }
            #pragma unroll
            for (int mi = 0; mi < 4; mi++)
                #pragma unroll
                for (int ni = 0; ni < 4; ni++)
                    mma1688(acc[mi][ni], af[mi], bf[ni]);
        }
        st = (st + 1 == 3) ? 0 : st + 1;
        __syncthreads();
    }

    // Epilogue
    #pragma unroll
    for (int mi = 0; mi < 4; mi++) {
        #pragma unroll
        for (int ni = 0; ni < 4; ni++) {
            const int cc = nBase + wn + ni * 8 + 2 * t4;
            const float b0 = bias[cc], b1 = bias[cc + 1];
            #pragma unroll
            for (int h = 0; h < 2; h++) {
                const int row = mBase + wm + mi * 16 + g + h * 8;
                float v0 = acc[mi][ni][2 * h + 0] + b0;
                float v1 = acc[mi][ni][2 * h + 1] + b1;
                if (RES) {
                    const float* rr = Rs + (size_t)row * N + cc;
                    v0 += rr[0]; v1 += rr[1];
                }
                if (RELU) { v0 = fmaxf(v0, 0.0f); v1 = fmaxf(v1, 0.0f); }
                if (ROUND) { v0 = tf32rf(v0); v1 = tf32rf(v1); }
                float2 o; o.x = v0; o.y = v1;
                *(float2*)(C + (size_t)row * N + cc) = o;
            }
        }
    }
}

// ===========================================================================
// Tensor-core flash attention (tf32 mma.sync); output rounded (feeds proj A)
// ===========================================================================
#define AQ_S 68
#define AV_S 72

__global__ void __launch_bounds__(128)
attn_mma_kernel(const float* __restrict__ qkv, float* __restrict__ out) {
    extern __shared__ uint32_t asmem[];
    uint32_t* Qs = asmem;                     // 128 x 68
    uint32_t* Ks = Qs + 128 * AQ_S;           // 64 x 68
    uint32_t* Vs = Ks + 64 * AQ_S;            // 64 x 72
    uint32_t* Ss = Vs + 64 * AV_S;            // 128 x 68
    float* rowM = (float*)(Ss + 128 * AQ_S);
    float* rowL = rowM + 128;
    float* rowA = rowL + 128;

    const int t = threadIdx.x;
    const int wid = t >> 5;
    const int lid = t & 31;
    const int g = lid >> 2, t4 = lid & 3;
    const int h = blockIdx.y;
    const int qb = blockIdx.x * 128;
    const int wrow = wid * 32;

    for (int i = t; i < 128 * 16; i += 128) {
        int r = i >> 4, d4 = (i & 15) * 4;
        float4 q = *(const float4*)(qkv + (size_t)(qb + r) * 1536 + h * 64 + d4);
        uint32_t* dst = &Qs[r * AQ_S + d4];
        dst[0] = tf32r(q.x * 0.125f); dst[1] = tf32r(q.y * 0.125f);
        dst[2] = tf32r(q.z * 0.125f); dst[3] = tf32r(q.w * 0.125f);
    }
    rowM[t] = -1e30f;
    rowL[t] = 0.0f;

    float o[2][8][4];
    #pragma unroll
    for (int mi = 0; mi < 2; mi++)
        #pragma unroll
        for (int ni = 0; ni < 8; ni++)
            #pragma unroll
            for (int r = 0; r < 4; r++) o[mi][ni][r] = 0.0f;

    for (int kb = 0; kb < NSEQ; kb += 64) {
        __syncthreads();
        for (int i = t; i < 64 * 16; i += 128) {
            int r = i >> 4, d4 = (i & 15) * 4;
            const float* base = qkv + (size_t)(kb + r) * 1536 + h * 64 + d4;
            float4 kv = *(const float4*)(base + 512);
            float4 vv = *(const float4*)(base + 1024);
            uint32_t* kd = &Ks[r * AQ_S + d4];
            kd[0] = tf32r(kv.x); kd[1] = tf32r(kv.y);
            kd[2] = tf32r(kv.z); kd[3] = tf32r(kv.w);
            uint32_t* vd = &Vs[r * AV_S + d4];
            vd[0] = tf32r(vv.x); vd[1] = tf32r(vv.y);
            vd[2] = tf32r(vv.z); vd[3] = tf32r(vv.w);
        }
        __syncthreads();

        float sf[2][8][4];
        #pragma unroll
        for (int mi = 0; mi < 2; mi++)
            #pragma unroll
            for (int ni = 0; ni < 8; ni++)
                #pragma unroll
                for (int r = 0; r < 4; r++) sf[mi][ni][r] = 0.0f;

        #pragma unroll
        for (int ks = 0; ks < 64; ks += 8) {
            uint32_t af[2][4];
            #pragma unroll
            for (int mi = 0; mi < 2; mi++) {
                int base = (wrow + mi * 16 + g) * AQ_S + ks + t4;
                af[mi][0] = Qs[base];
                af[mi][1] = Qs[base + 8 * AQ_S];
                af[mi][2] = Qs[base + 4];
                af[mi][3] = Qs[base + 8 * AQ_S + 4];
            }
            #pragma unroll
            for (int ni = 0; ni < 8; ni++) {
                uint32_t bf[2];
                int base = (ni * 8 + g) * AQ_S + ks + t4;
                bf[0] = Ks[base];
                bf[1] = Ks[base + 4];
                mma1688(sf[0][ni], af[0], bf);
                mma1688(sf[1][ni], af[1], bf);
            }
        }
        #pragma unroll
        for (int mi = 0; mi < 2; mi++) {
            #pragma unroll
            for (int ni = 0; ni < 8; ni++) {
                int r0 = wrow + mi * 16 + g;
                int cc = ni * 8 + 2 * t4;
                float2 lo; lo.x = sf[mi][ni][0]; lo.y = sf[mi][ni][1];
                float2 hi; hi.x = sf[mi][ni][2]; hi.y = sf[mi][ni][3];
                *(float2*)&((float*)Ss)[r0 * AQ_S + cc] = lo;
                *(float2*)&((float*)Ss)[(r0 + 8) * AQ_S + cc] = hi;
            }
        }
        __syncthreads();

        {
            float* Sr = (float*)Ss + t * AQ_S;
            uint32_t* Pr = Ss + t * AQ_S;
            float mprev = rowM[t];
            float mx = mprev;
            #pragma unroll 8
            for (int j = 0; j < 64; j++) mx = fmaxf(mx, Sr[j]);
            float al = __expf(mprev - mx);
            float sum = 0.0f;
            #pragma unroll 8
            for (int j = 0; j < 64; j++) {
                float p = __expf(Sr[j] - mx);
                sum += p;
                Pr[j] = tf32r(p);
            }
            rowL[t] = rowL[t] * al + sum;
            rowM[t] = mx;
            rowA[t] = al;
        }
        __syncthreads();

        #pragma unroll
        for (int mi = 0; mi < 2; mi++) {
            float a0 = rowA[wrow + mi * 16 + g];
            float a1 = rowA[wrow + mi * 16 + g + 8];
            #pragma unroll
            for (int ni = 0; ni < 8; ni++) {
                o[mi][ni][0] *= a0; o[mi][ni][1] *= a0;
                o[mi][ni][2] *= a1; o[mi][ni][3] *= a1;
            }
        }
        #pragma unroll
        for (int ks = 0; ks < 64; ks += 8) {
            uint32_t af[2][4];
            #pragma unroll
            for (int mi = 0; mi < 2; mi++) {
                int base = (wrow + mi * 16 + g) * AQ_S + ks + t4;
                af[mi][0] = Ss[base];
                af[mi][1] = Ss[base + 8 * AQ_S];
                af[mi][2] = Ss[base + 4];
                af[mi][3] = Ss[base + 8 * AQ_S + 4];
            }
            #pragma unroll
            for (int ni = 0; ni < 8; ni++) {
                uint32_t bf[2];
                bf[0] = Vs[(ks + t4) * AV_S + ni * 8 + g];
                bf[1] = Vs[(ks + t4 + 4) * AV_S + ni * 8 + g];
                mma1688(o[0][ni], af[0], bf);
                mma1688(o[1][ni], af[1], bf);
            }
        }
    }

    #pragma unroll
    for (int mi = 0; mi < 2; mi++) {
        float inv0 = 1.0f / rowL[wrow + mi * 16 + g];
        float inv1 = 1.0f / rowL[wrow + mi * 16 + g + 8];
        #pragma unroll
        for (int ni = 0; ni < 8; ni++) {
            int cc = h * 64 + ni * 8 + 2 * t4;
            int r0 = qb + wrow + mi * 16 + g;
            float2 lo; lo.x = tf32rf(o[mi][ni][0] * inv0); lo.y = tf32rf(o[mi][ni][1] * inv0);
            float2 hi; hi.x = tf32rf(o[mi][ni][2] * inv1); hi.y = tf32rf(o[mi][ni][3] * inv1);
            *(float2*)(out + (size_t)r0 * EDIM + cc) = lo;
            *(float2*)(out + (size_t)(r0 + 8) * EDIM + cc) = hi;
        }
    }
}

static const int ATTN_SMEM =
    (128 * AQ_S + 64 * AQ_S + 64 * AV_S + 128 * AQ_S) * 4 + 3 * 128 * 4;

extern "C" void kernel_launch(void* const* d_in, const int* in_sizes, int n_in,
                              void* d_out, int out_size) {
    const float* x      = (const float*)d_in[0];
    const float* ln_g   = (const float*)d_in[1];
    const float* ln_b   = (const float*)d_in[2];
    const float* qkv_w  = (const float*)d_in[3];
    const float* qkv_b  = (const float*)d_in[4];
    const float* proj_w = (const float*)d_in[5];
    const float* proj_b = (const float*)d_in[6];
    const float* fc1_w  = (const float*)d_in[7];
    const float* fc1_b  = (const float*)d_in[8];
    const float* fc2_w  = (const float*)d_in[9];
    const float* fc2_b  = (const float*)d_in[10];
    const float* fc3_w  = (const float*)d_in[11];
    const float* fc3_b  = (const float*)d_in[12];
    float* out = (float*)d_out;

    float *h1, *qkvb, *attnb, *x1, *h2, *m1, *m2;
    float *wqkv, *wproj, *w1, *w2, *w3;
    cudaGetSymbolAddress((void**)&h1, g_h1);
    cudaGetSymbolAddress((void**)&qkvb, g_qkv);
    cudaGetSymbolAddress((void**)&attnb, g_attn);
    cudaGetSymbolAddress((void**)&x1, g_x1);
    cudaGetSymbolAddress((void**)&h2, g_h2);
    cudaGetSymbolAddress((void**)&m1, g_m1);
    cudaGetSymbolAddress((void**)&m2, g_m2);
    cudaGetSymbolAddress((void**)&wqkv, g_wqkv);
    cudaGetSymbolAddress((void**)&wproj, g_wproj);
    cudaGetSymbolAddress((void**)&w1, g_w1);
    cudaGetSymbolAddress((void**)&w2, g_w2);
    cudaGetSymbolAddress((void**)&w3, g_w3);

    cudaFuncSetAttribute(attn_mma_kernel, cudaFuncAttributeMaxDynamicSharedMemorySize,
                         ATTN_SMEM);
    cudaFuncSetAttribute(mma_gemm<false, false, false>,
                         cudaFuncAttributeMaxDynamicSharedMemorySize, G_SMEM_BYTES);
    cudaFuncSetAttribute(mma_gemm<false, true, false>,
                         cudaFuncAttributeMaxDynamicSharedMemorySize, G_SMEM_BYTES);
    cudaFuncSetAttribute(mma_gemm<true, false, true>,
                         cudaFuncAttributeMaxDynamicSharedMemorySize, G_SMEM_BYTES);

    // 0. Pre-round weights to tf32-exact fp32
    {
        const int thr = 256;
        round_w_kernel<<<(3 * EDIM * EDIM / 4 + thr - 1) / thr, thr>>>(qkv_w, wqkv,
                                                                       3 * EDIM * EDIM / 4);
        round_w_kernel<<<(EDIM * EDIM / 4 + thr - 1) / thr, thr>>>(proj_w, wproj,
                                                                   EDIM * EDIM / 4);
        round_w_kernel<<<(HDIM * EDIM / 4 + thr - 1) / thr, thr>>>(fc1_w, w1,
                                                                   HDIM * EDIM / 4);
        round_w_kernel<<<(HDIM * HDIM / 4 + thr - 1) / thr, thr>>>(fc2_w, w2,
                                                                   HDIM * HDIM / 4);
        round_w_kernel<<<(EDIM * HDIM / 4 + thr - 1) / thr, thr>>>(fc3_w, w3,
                                                                   EDIM * HDIM / 4);
    }

    // 1. LN1 (rounded output)
    ln_kernel<<<NSEQ, 128>>>(x, ln_g, ln_b, h1);
    // 2. QKV
    mma_gemm<false, false, false><<<dim3(12, 32), 256, G_SMEM_BYTES>>>(
        h1, wqkv, qkv_b, nullptr, qkvb, NSEQ, 3 * EDIM, EDIM);
    // 3. Attention (rounded output)
    attn_mma_kernel<<<dim3(32, NHEAD), 128, ATTN_SMEM>>>(qkvb, attnb);
    // 4. proj + residual (full fp32 out)
    mma_gemm<false, true, false><<<dim3(4, 32), 256, G_SMEM_BYTES>>>(
        attnb, wproj, proj_b, x, x1, NSEQ, EDIM, EDIM);
    // 5. LN2 (rounded output)
    ln_kernel<<<NSEQ, 128>>>(x1, ln_g, ln_b, h2);
    // 6. fc1 + relu (rounded output; feeds fc2 A)
    mma_gemm<true, false, true><<<dim3(16, 32), 256, G_SMEM_BYTES>>>(
        h2, w1, fc1_b, nullptr, m1, NSEQ, HDIM, EDIM);
    // 7. fc2 + relu (rounded output; feeds fc3 A)
    mma_gemm<true, false, true><<<dim3(16, 32), 256, G_SMEM_BYTES>>>(
        m1, w2, fc2_b, nullptr, m2, NSEQ, HDIM, HDIM);
    // 8. fc3 + bias + residual -> out (full fp32)
    mma_gemm<false, true, false><<<dim3(4, 32), 256, G_SMEM_BYTES>>>(
        m2, w3, fc3_b, x1, out, NSEQ, EDIM, HDIM);
}

// round 11
// speedup vs baseline: 1.0384x; 1.0384x over previous
#include <cuda_runtime.h>
#include <cstdint>
#include <math.h>

// Problem constants
#define EDIM 512
#define NSEQ 4096
#define NHEAD 8
#define HDIM 2048

typedef unsigned long long u64;

// ---- tf32 mma.sync helpers (family-agnostic PTX, works on compute_103) ----
__device__ __forceinline__ uint32_t tf32r(float f) {
    uint32_t u;
    asm("cvt.rna.tf32.f32 %0, %1;" : "=r"(u) : "f"(f));
    return u;
}
__device__ __forceinline__ float tf32rf(float f) {
    return __uint_as_float(tf32r(f));
}
__device__ __forceinline__ void mma1688(float* c, const uint32_t* a, const uint32_t* b) {
    asm volatile(
        "mma.sync.aligned.m16n8k8.row.col.f32.tf32.tf32.f32 "
        "{%0,%1,%2,%3}, {%4,%5,%6,%7}, {%8,%9}, {%0,%1,%2,%3};"
        : "+f"(c[0]), "+f"(c[1]), "+f"(c[2]), "+f"(c[3])
        : "r"(a[0]), "r"(a[1]), "r"(a[2]), "r"(a[3]), "r"(b[0]), "r"(b[1]));
}
__device__ __forceinline__ void ldsm_x4(uint32_t* r, uint32_t saddr) {
    asm volatile("ldmatrix.sync.aligned.m8n8.x4.shared.b16 {%0,%1,%2,%3}, [%4];"
                 : "=r"(r[0]), "=r"(r[1]), "=r"(r[2]), "=r"(r[3]) : "r"(saddr));
}
__device__ __forceinline__ uint32_t smem_u32(const void* p) {
    uint32_t a;
    asm("{ .reg .u64 t; cvta.to.shared.u64 t, %1; cvt.u32.u64 %0, t; }" : "=r"(a) : "l"(p));
    return a;
}
__device__ __forceinline__ void cpa16(uint32_t s, const void* g) {
    asm volatile("cp.async.cg.shared.global [%0], [%1], 16;" :: "r"(s), "l"(g));
}
#define CP_COMMIT() asm volatile("cp.async.commit_group;" ::: "memory")
#define CP_WAIT0()  asm volatile("cp.async.wait_group 0;" ::: "memory")
#define CP_WAIT1()  asm volatile("cp.async.wait_group 1;" ::: "memory")

// Scratch (alloc-free rule: __device__ globals)
__device__ float g_h1[NSEQ * EDIM];
__device__ float g_qkv[NSEQ * 3 * EDIM];
__device__ float g_attn[NSEQ * EDIM];
__device__ float g_x1[NSEQ * EDIM];
__device__ float g_h2[NSEQ * EDIM];
__device__ float g_m1[NSEQ * HDIM];
__device__ float g_m2[NSEQ * HDIM];
// tf32-pre-rounded weights
__device__ float g_wqkv[3 * EDIM * EDIM];
__device__ float g_wproj[EDIM * EDIM];
__device__ float g_w1[HDIM * EDIM];
__device__ float g_w2[HDIM * HDIM];
__device__ float g_w3[EDIM * HDIM];

// ===========================================================================
// Weight pre-rounding (fp32 -> tf32-exact fp32), float4 grid-stride
// ===========================================================================
__global__ void round_w_kernel(const float* __restrict__ src, float* __restrict__ dst,
                               int n4) {
    int i = blockIdx.x * blockDim.x + threadIdx.x;
    if (i < n4) {
        float4 v = ((const float4*)src)[i];
        v.x = tf32rf(v.x); v.y = tf32rf(v.y); v.z = tf32rf(v.z); v.w = tf32rf(v.w);
        ((float4*)dst)[i] = v;
    }
}

// ===========================================================================
// LayerNorm (output rounded to tf32-exact fp32; feeds GEMM A only)
// ===========================================================================
__global__ void ln_kernel(const float* __restrict__ X, const float* __restrict__ g,
                          const float* __restrict__ b, float* __restrict__ Y) {
    const int row = blockIdx.x;
    const int t = threadIdx.x;  // 128 threads
    const float4* Xv = (const float4*)(X + (size_t)row * EDIM);
    float4 v = Xv[t];

    __shared__ float red[4];
    float s = v.x + v.y + v.z + v.w;
    #pragma unroll
    for (int o = 16; o > 0; o >>= 1) s += __shfl_down_sync(0xffffffffu, s, o);
    if ((t & 31) == 0) red[t >> 5] = s;
    __syncthreads();
    float mean = (red[0] + red[1] + red[2] + red[3]) * (1.0f / EDIM);
    __syncthreads();

    float dx = v.x - mean, dy = v.y - mean, dz = v.z - mean, dw = v.w - mean;
    float s2 = dx * dx + dy * dy + dz * dz + dw * dw;
    #pragma unroll
    for (int o = 16; o > 0; o >>= 1) s2 += __shfl_down_sync(0xffffffffu, s2, o);
    if ((t & 31) == 0) red[t >> 5] = s2;
    __syncthreads();
    float var = (red[0] + red[1] + red[2] + red[3]) * (1.0f / EDIM);
    float rs = rsqrtf(var + 1e-5f);

    float4 gv = ((const float4*)g)[t];
    float4 bv = ((const float4*)b)[t];
    float4 o4;
    o4.x = tf32rf(dx * rs * gv.x + bv.x);
    o4.y = tf32rf(dy * rs * gv.y + bv.y);
    o4.z = tf32rf(dz * rs * gv.z + bv.z);
    o4.w = tf32rf(dw * rs * gv.w + bv.w);
    ((float4*)(Y + (size_t)row * EDIM))[t] = o4;
}

// ===========================================================================
// tf32 mma.sync GEMM: C[M,N] = A[M,K]*B[N,K]^T (+bias, +res, +relu, +round)
// CTA 128x128, 8 warps (2x4), warp tile 64x32, K-chunk 16.
// 3-stage cp.async pipeline; ldmatrix.x4 fragment loads (1 LDSM = 1 A-frag,
// 1 LDSM = 2 B-frags). Inputs are tf32-exact fp32 -> raw-bit MMA feed exact.
// ===========================================================================
#define SMS 20                 // smem row stride (uint32)
#define G_STAGE (128 * SMS)    // uint32 per matrix per stage
#define G_SMEM_BYTES (3 * 2 * G_STAGE * 4)   // 61440

template <bool RELU, bool RES, bool ROUND>
__global__ void __launch_bounds__(256, 2)
mma_gemm(const float* __restrict__ A, const float* __restrict__ B,
         const float* __restrict__ bias, const float* __restrict__ Rs,
         float* __restrict__ C, int M, int N, int K) {
    extern __shared__ uint32_t dsm[];
    uint32_t* sA = dsm;                    // 3 stages x 128*SMS
    uint32_t* sB = dsm + 3 * G_STAGE;      // 3 stages x 128*SMS

    const int t = threadIdx.x;
    const int wid = t >> 5;
    const int lid = t & 31;
    const int mBase = blockIdx.y * 128;
    const int nBase = blockIdx.x * 128;

    const int wm = (wid >> 2) * 64;
    const int wn = (wid & 3) * 32;
    const int g = lid >> 2;
    const int t4 = lid & 3;

    float acc[4][4][4];
    #pragma unroll
    for (int mi = 0; mi < 4; mi++)
        #pragma unroll
        for (int ni = 0; ni < 4; ni++)
            #pragma unroll
            for (int r = 0; r < 4; r++) acc[mi][ni][r] = 0.0f;

    // cp.async loader indexing
    const int s0 = t * 2;
    const int lrow0 = s0 >> 2, lq0 = (s0 & 3) * 4;
    const int lrow1 = (s0 + 1) >> 2, lq1 = ((s0 + 1) & 3) * 4;

    const float* Ap0 = A + (size_t)(mBase + lrow0) * K + lq0;
    const float* Ap1 = A + (size_t)(mBase + lrow1) * K + lq1;
    const float* Bp0 = B + (size_t)(nBase + lrow0) * K + lq0;
    const float* Bp1 = B + (size_t)(nBase + lrow1) * K + lq1;
    uint32_t sa0[3], sa1[3], sb0[3], sb1[3];
    #pragma unroll
    for (int st = 0; st < 3; st++) {
        sa0[st] = smem_u32(&sA[st * G_STAGE + lrow0 * SMS + lq0]);
        sa1[st] = smem_u32(&sA[st * G_STAGE + lrow1 * SMS + lq1]);
        sb0[st] = smem_u32(&sB[st * G_STAGE + lrow0 * SMS + lq0]);
        sb1[st] = smem_u32(&sB[st * G_STAGE + lrow1 * SMS + lq1]);
    }

    // ldmatrix per-lane base addresses (within stage 0), in uint32 elems
    //  A m16k8 frag (x4): lanes 0-15 -> row (lid&15), k-half 0;
    //                     lanes 16-31 -> row (lid&15), k-half 1 (+4 elems)
    const int a_elem = (wm + (lid & 15)) * SMS + ((lid >> 4) << 2);
    //  B 2x n8k8 frags (x4): M0/M1 = n-rows [nb, nb+8) k-halves 0/1,
    //                        M2/M3 = n-rows [nb+8, nb+16) k-halves 0/1
    const int b_elem = (wn + ((lid >> 4) << 3) + (lid & 7)) * SMS + (((lid >> 3) & 1) << 2);
    uint32_t aB[3], bB[3];
    #pragma unroll
    for (int st = 0; st < 3; st++) {
        aB[st] = smem_u32(&sA[st * G_STAGE + a_elem]);
        bB[st] = smem_u32(&sB[st * G_STAGE + b_elem]);
    }

    auto issue_chunk = [&](int c, int st) {
        const int k0 = c << 4;
        cpa16(sa0[st], Ap0 + k0);
        cpa16(sa1[st], Ap1 + k0);
        cpa16(sb0[st], Bp0 + k0);
        cpa16(sb1[st], Bp1 + k0);
    };

    const int T = K >> 4;
    issue_chunk(0, 0); CP_COMMIT();
    if (T > 1) { issue_chunk(1, 1); CP_COMMIT(); }

    int st = 0;
    for (int c = 0; c < T; c++) {
        if (c + 1 < T) CP_WAIT1(); else CP_WAIT0();
        __syncthreads();
        if (c + 2 < T) { issue_chunk(c + 2, (st + 2 >= 3) ? st - 1 : st + 2); CP_COMMIT(); }

        const uint32_t aBs = aB[st];
        const uint32_t bBs = bB[st];
        #pragma unroll
        for (int ks = 0; ks < 16; ks += 8) {
            uint32_t af[4][4], bfr[2][4];
            #pragma unroll
            for (int mi = 0; mi < 4; mi++)
                ldsm_x4(af[mi], aBs + (mi * 16 * SMS + ks) * 4);
            #pragma unroll
            for (int nb = 0; nb < 2; nb++)
                ldsm_x4(bfr[nb], bBs + (nb * 16 * SMS + ks) * 4);
            #pragma unroll
            for (int mi = 0; mi < 4; mi++)
                #pragma unroll
                for (int ni = 0; ni < 4; ni++)
                    mma1688(acc[mi][ni], af[mi], &bfr[ni >> 1][(ni & 1) * 2]);
        }
        st = (st + 1 == 3) ? 0 : st + 1;
        __syncthreads();
    }

    // Epilogue
    #pragma unroll
    for (int mi = 0; mi < 4; mi++) {
        #pragma unroll
        for (int ni = 0; ni < 4; ni++) {
            const int cc = nBase + wn + ni * 8 + 2 * t4;
            const float b0 = bias[cc], b1 = bias[cc + 1];
            #pragma unroll
            for (int h = 0; h < 2; h++) {
                const int row = mBase + wm + mi * 16 + g + h * 8;
                float v0 = acc[mi][ni][2 * h + 0] + b0;
                float v1 = acc[mi][ni][2 * h + 1] + b1;
                if (RES) {
                    const float* rr = Rs + (size_t)row * N + cc;
                    v0 += rr[0]; v1 += rr[1];
                }
                if (RELU) { v0 = fmaxf(v0, 0.0f); v1 = fmaxf(v1, 0.0f); }
                if (ROUND) { v0 = tf32rf(v0); v1 = tf32rf(v1); }
                float2 o; o.x = v0; o.y = v1;
                *(float2*)(C + (size_t)row * N + cc) = o;
            }
        }
    }
}

// ===========================================================================
// Tensor-core flash attention (tf32 mma.sync); output rounded (feeds proj A)
// ===========================================================================
#define AQ_S 68
#define AV_S 72

__global__ void __launch_bounds__(128)
attn_mma_kernel(const float* __restrict__ qkv, float* __restrict__ out) {
    extern __shared__ uint32_t asmem[];
    uint32_t* Qs = asmem;                     // 128 x 68
    uint32_t* Ks = Qs + 128 * AQ_S;           // 64 x 68
    uint32_t* Vs = Ks + 64 * AQ_S;            // 64 x 72
    uint32_t* Ss = Vs + 64 * AV_S;            // 128 x 68
    float* rowM = (float*)(Ss + 128 * AQ_S);
    float* rowL = rowM + 128;
    float* rowA = rowL + 128;

    const int t = threadIdx.x;
    const int wid = t >> 5;
    const int lid = t & 31;
    const int g = lid >> 2, t4 = lid & 3;
    const int h = blockIdx.y;
    const int qb = blockIdx.x * 128;
    const int wrow = wid * 32;

    for (int i = t; i < 128 * 16; i += 128) {
        int r = i >> 4, d4 = (i & 15) * 4;
        float4 q = *(const float4*)(qkv + (size_t)(qb + r) * 1536 + h * 64 + d4);
        uint32_t* dst = &Qs[r * AQ_S + d4];
        dst[0] = tf32r(q.x * 0.125f); dst[1] = tf32r(q.y * 0.125f);
        dst[2] = tf32r(q.z * 0.125f); dst[3] = tf32r(q.w * 0.125f);
    }
    rowM[t] = -1e30f;
    rowL[t] = 0.0f;

    float o[2][8][4];
    #pragma unroll
    for (int mi = 0; mi < 2; mi++)
        #pragma unroll
        for (int ni = 0; ni < 8; ni++)
            #pragma unroll
            for (int r = 0; r < 4; r++) o[mi][ni][r] = 0.0f;

    for (int kb = 0; kb < NSEQ; kb += 64) {
        __syncthreads();
        for (int i = t; i < 64 * 16; i += 128) {
            int r = i >> 4, d4 = (i & 15) * 4;
            const float* base = qkv + (size_t)(kb + r) * 1536 + h * 64 + d4;
            float4 kv = *(const float4*)(base + 512);
            float4 vv = *(const float4*)(base + 1024);
            uint32_t* kd = &Ks[r * AQ_S + d4];
            kd[0] = tf32r(kv.x); kd[1] = tf32r(kv.y);
            kd[2] = tf32r(kv.z); kd[3] = tf32r(kv.w);
            uint32_t* vd = &Vs[r * AV_S + d4];
            vd[0] = tf32r(vv.x); vd[1] = tf32r(vv.y);
            vd[2] = tf32r(vv.z); vd[3] = tf32r(vv.w);
        }
        __syncthreads();

        float sf[2][8][4];
        #pragma unroll
        for (int mi = 0; mi < 2; mi++)
            #pragma unroll
            for (int ni = 0; ni < 8; ni++)
                #pragma unroll
                for (int r = 0; r < 4; r++) sf[mi][ni][r] = 0.0f;

        #pragma unroll
        for (int ks = 0; ks < 64; ks += 8) {
            uint32_t af[2][4];
            #pragma unroll
            for (int mi = 0; mi < 2; mi++) {
                int base = (wrow + mi * 16 + g) * AQ_S + ks + t4;
                af[mi][0] = Qs[base];
                af[mi][1] = Qs[base + 8 * AQ_S];
                af[mi][2] = Qs[base + 4];
                af[mi][3] = Qs[base + 8 * AQ_S + 4];
            }
            #pragma unroll
            for (int ni = 0; ni < 8; ni++) {
                uint32_t bf[2];
                int base = (ni * 8 + g) * AQ_S + ks + t4;
                bf[0] = Ks[base];
                bf[1] = Ks[base + 4];
                mma1688(sf[0][ni], af[0], bf);
                mma1688(sf[1][ni], af[1], bf);
            }
        }
        #pragma unroll
        for (int mi = 0; mi < 2; mi++) {
            #pragma unroll
            for (int ni = 0; ni < 8; ni++) {
                int r0 = wrow + mi * 16 + g;
                int cc = ni * 8 + 2 * t4;
                float2 lo; lo.x = sf[mi][ni][0]; lo.y = sf[mi][ni][1];
                float2 hi; hi.x = sf[mi][ni][2]; hi.y = sf[mi][ni][3];
                *(float2*)&((float*)Ss)[r0 * AQ_S + cc] = lo;
                *(float2*)&((float*)Ss)[(r0 + 8) * AQ_S + cc] = hi;
            }
        }
        __syncthreads();

        {
            float* Sr = (float*)Ss + t * AQ_S;
            uint32_t* Pr = Ss + t * AQ_S;
            float mprev = rowM[t];
            float mx = mprev;
            #pragma unroll 8
            for (int j = 0; j < 64; j++) mx = fmaxf(mx, Sr[j]);
            float al = __expf(mprev - mx);
            float sum = 0.0f;
            #pragma unroll 8
            for (int j = 0; j < 64; j++) {
                float p = __expf(Sr[j] - mx);
                sum += p;
                Pr[j] = tf32r(p);
            }
            rowL[t] = rowL[t] * al + sum;
            rowM[t] = mx;
            rowA[t] = al;
        }
        __syncthreads();

        #pragma unroll
        for (int mi = 0; mi < 2; mi++) {
            float a0 = rowA[wrow + mi * 16 + g];
            float a1 = rowA[wrow + mi * 16 + g + 8];
            #pragma unroll
            for (int ni = 0; ni < 8; ni++) {
                o[mi][ni][0] *= a0; o[mi][ni][1] *= a0;
                o[mi][ni][2] *= a1; o[mi][ni][3] *= a1;
            }
        }
        #pragma unroll
        for (int ks = 0; ks < 64; ks += 8) {
            uint32_t af[2][4];
            #pragma unroll
            for (int mi = 0; mi < 2; mi++) {
                int base = (wrow + mi * 16 + g) * AQ_S + ks + t4;
                af[mi][0] = Ss[base];
                af[mi][1] = Ss[base + 8 * AQ_S];
                af[mi][2] = Ss[base + 4];
                af[mi][3] = Ss[base + 8 * AQ_S + 4];
            }
            #pragma unroll
            for (int ni = 0; ni < 8; ni++) {
                uint32_t bf[2];
                bf[0] = Vs[(ks + t4) * AV_S + ni * 8 + g];
                bf[1] = Vs[(ks + t4 + 4) * AV_S + ni * 8 + g];
                mma1688(o[0][ni], af[0], bf);
                mma1688(o[1][ni], af[1], bf);
            }
        }
    }

    #pragma unroll
    for (int mi = 0; mi < 2; mi++) {
        float inv0 = 1.0f / rowL[wrow + mi * 16 + g];
        float inv1 = 1.0f / rowL[wrow + mi * 16 + g + 8];
        #pragma unroll
        for (int ni = 0; ni < 8; ni++) {
            int cc = h * 64 + ni * 8 + 2 * t4;
            int r0 = qb + wrow + mi * 16 + g;
            float2 lo; lo.x = tf32rf(o[mi][ni][0] * inv0); lo.y = tf32rf(o[mi][ni][1] * inv0);
            float2 hi; hi.x = tf32rf(o[mi][ni][2] * inv1); hi.y = tf32rf(o[mi][ni][3] * inv1);
            *(float2*)(out + (size_t)r0 * EDIM + cc) = lo;
            *(float2*)(out + (size_t)(r0 + 8) * EDIM + cc) = hi;
        }
    }
}

static const int ATTN_SMEM =
    (128 * AQ_S + 64 * AQ_S + 64 * AV_S + 128 * AQ_S) * 4 + 3 * 128 * 4;

extern "C" void kernel_launch(void* const* d_in, const int* in_sizes, int n_in,
                              void* d_out, int out_size) {
    const float* x      = (const float*)d_in[0];
    const float* ln_g   = (const float*)d_in[1];
    const float* ln_b   = (const float*)d_in[2];
    const float* qkv_w  = (const float*)d_in[3];
    const float* qkv_b  = (const float*)d_in[4];
    const float* proj_w = (const float*)d_in[5];
    const float* proj_b = (const float*)d_in[6];
    const float* fc1_w  = (const float*)d_in[7];
    const float* fc1_b  = (const float*)d_in[8];
    const float* fc2_w  = (const float*)d_in[9];
    const float* fc2_b  = (const float*)d_in[10];
    const float* fc3_w  = (const float*)d_in[11];
    const float* fc3_b  = (const float*)d_in[12];
    float* out = (float*)d_out;

    float *h1, *qkvb, *attnb, *x1, *h2, *m1, *m2;
    float *wqkv, *wproj, *w1, *w2, *w3;
    cudaGetSymbolAddress((void**)&h1, g_h1);
    cudaGetSymbolAddress((void**)&qkvb, g_qkv);
    cudaGetSymbolAddress((void**)&attnb, g_attn);
    cudaGetSymbolAddress((void**)&x1, g_x1);
    cudaGetSymbolAddress((void**)&h2, g_h2);
    cudaGetSymbolAddress((void**)&m1, g_m1);
    cudaGetSymbolAddress((void**)&m2, g_m2);
    cudaGetSymbolAddress((void**)&wqkv, g_wqkv);
    cudaGetSymbolAddress((void**)&wproj, g_wproj);
    cudaGetSymbolAddress((void**)&w1, g_w1);
    cudaGetSymbolAddress((void**)&w2, g_w2);
    cudaGetSymbolAddress((void**)&w3, g_w3);

    cudaFuncSetAttribute(attn_mma_kernel, cudaFuncAttributeMaxDynamicSharedMemorySize,
                         ATTN_SMEM);
    cudaFuncSetAttribute(mma_gemm<false, false, false>,
                         cudaFuncAttributeMaxDynamicSharedMemorySize, G_SMEM_BYTES);
    cudaFuncSetAttribute(mma_gemm<false, true, false>,
                         cudaFuncAttributeMaxDynamicSharedMemorySize, G_SMEM_BYTES);
    cudaFuncSetAttribute(mma_gemm<true, false, true>,
                         cudaFuncAttributeMaxDynamicSharedMemorySize, G_SMEM_BYTES);

    // 0. Pre-round weights to tf32-exact fp32
    {
        const int thr = 256;
        round_w_kernel<<<(3 * EDIM * EDIM / 4 + thr - 1) / thr, thr>>>(qkv_w, wqkv,
                                                                       3 * EDIM * EDIM / 4);
        round_w_kernel<<<(EDIM * EDIM / 4 + thr - 1) / thr, thr>>>(proj_w, wproj,
                                                                   EDIM * EDIM / 4);
        round_w_kernel<<<(HDIM * EDIM / 4 + thr - 1) / thr, thr>>>(fc1_w, w1,
                                                                   HDIM * EDIM / 4);
        round_w_kernel<<<(HDIM * HDIM / 4 + thr - 1) / thr, thr>>>(fc2_w, w2,
                                                                   HDIM * HDIM / 4);
        round_w_kernel<<<(EDIM * HDIM / 4 + thr - 1) / thr, thr>>>(fc3_w, w3,
                                                                   EDIM * HDIM / 4);
    }

    // 1. LN1 (rounded output)
    ln_kernel<<<NSEQ, 128>>>(x, ln_g, ln_b, h1);
    // 2. QKV
    mma_gemm<false, false, false><<<dim3(12, 32), 256, G_SMEM_BYTES>>>(
        h1, wqkv, qkv_b, nullptr, qkvb, NSEQ, 3 * EDIM, EDIM);
    // 3. Attention (rounded output)
    attn_mma_kernel<<<dim3(32, NHEAD), 128, ATTN_SMEM>>>(qkvb, attnb);
    // 4. proj + residual (full fp32 out)
    mma_gemm<false, true, false><<<dim3(4, 32), 256, G_SMEM_BYTES>>>(
        attnb, wproj, proj_b, x, x1, NSEQ, EDIM, EDIM);
    // 5. LN2 (rounded output)
    ln_kernel<<<NSEQ, 128>>>(x1, ln_g, ln_b, h2);
    // 6. fc1 + relu (rounded output; feeds fc2 A)
    mma_gemm<true, false, true><<<dim3(16, 32), 256, G_SMEM_BYTES>>>(
        h2, w1, fc1_b, nullptr, m1, NSEQ, HDIM, EDIM);
    // 7. fc2 + relu (rounded output; feeds fc3 A)
    mma_gemm<true, false, true><<<dim3(16, 32), 256, G_SMEM_BYTES>>>(
        m1, w2, fc2_b, nullptr, m2, NSEQ, HDIM, HDIM);
    // 8. fc3 + bias + residual -> out (full fp32)
    mma_gemm<false, true, false><<<dim3(4, 32), 256, G_SMEM_BYTES>>>(
        m2, w3, fc3_b, x1, out, NSEQ, EDIM, HDIM);
}

// round 12
// speedup vs baseline: 1.0427x; 1.0041x over previous
#include <cuda_runtime.h>
#include <cstdint>
#include <math.h>

// Problem constants
#define EDIM 512
#define NSEQ 4096
#define NHEAD 8
#define HDIM 2048

typedef unsigned long long u64;

// ---- tf32 mma.sync helpers (family-agnostic PTX, works on compute_103) ----
__device__ __forceinline__ uint32_t tf32r(float f) {
    uint32_t u;
    asm("cvt.rna.tf32.f32 %0, %1;" : "=r"(u) : "f"(f));
    return u;
}
__device__ __forceinline__ float tf32rf(float f) {
    return __uint_as_float(tf32r(f));
}
__device__ __forceinline__ void mma1688(float* c, const uint32_t* a, const uint32_t* b) {
    asm volatile(
        "mma.sync.aligned.m16n8k8.row.col.f32.tf32.tf32.f32 "
        "{%0,%1,%2,%3}, {%4,%5,%6,%7}, {%8,%9}, {%0,%1,%2,%3};"
        : "+f"(c[0]), "+f"(c[1]), "+f"(c[2]), "+f"(c[3])
        : "r"(a[0]), "r"(a[1]), "r"(a[2]), "r"(a[3]), "r"(b[0]), "r"(b[1]));
}
__device__ __forceinline__ void ldsm_x4(uint32_t* r, uint32_t saddr) {
    asm volatile("ldmatrix.sync.aligned.m8n8.x4.shared.b16 {%0,%1,%2,%3}, [%4];"
                 : "=r"(r[0]), "=r"(r[1]), "=r"(r[2]), "=r"(r[3]) : "r"(saddr));
}
__device__ __forceinline__ uint32_t smem_u32(const void* p) {
    uint32_t a;
    asm("{ .reg .u64 t; cvta.to.shared.u64 t, %1; cvt.u32.u64 %0, t; }" : "=r"(a) : "l"(p));
    return a;
}
__device__ __forceinline__ void cpa16(uint32_t s, const void* g) {
    asm volatile("cp.async.cg.shared.global [%0], [%1], 16;" :: "r"(s), "l"(g));
}
#define CP_COMMIT() asm volatile("cp.async.commit_group;" ::: "memory")
#define CP_WAIT0()  asm volatile("cp.async.wait_group 0;" ::: "memory")
#define CP_WAIT1()  asm volatile("cp.async.wait_group 1;" ::: "memory")

// Scratch (alloc-free rule: __device__ globals)
__device__ float g_h1[NSEQ * EDIM];
__device__ float g_qkv[NSEQ * 3 * EDIM];
__device__ float g_attn[NSEQ * EDIM];
__device__ float g_x1[NSEQ * EDIM];
__device__ float g_h2[NSEQ * EDIM];
__device__ float g_m1[NSEQ * HDIM];
__device__ float g_m2[NSEQ * HDIM];
// tf32-pre-rounded weights
__device__ float g_wqkv[3 * EDIM * EDIM];
__device__ float g_wproj[EDIM * EDIM];
__device__ float g_w1[HDIM * EDIM];
__device__ float g_w2[HDIM * HDIM];
__device__ float g_w3[EDIM * HDIM];

// ===========================================================================
// Weight pre-rounding, single fused kernel over 5 segments (float4 units)
//  qkv: 196608 | proj: 65536 | fc1: 262144 | fc2: 1048576 | fc3: 262144
// ===========================================================================
__global__ void round_w_all(const float* __restrict__ s0, float* __restrict__ d0,
                            const float* __restrict__ s1, float* __restrict__ d1,
                            const float* __restrict__ s2, float* __restrict__ d2,
                            const float* __restrict__ s3, float* __restrict__ d3,
                            const float* __restrict__ s4, float* __restrict__ d4) {
    int i = blockIdx.x * blockDim.x + threadIdx.x;
    const float* s; float* d; int off;
    if (i < 196608)       { s = s0; d = d0; off = i; }
    else if (i < 262144)  { s = s1; d = d1; off = i - 196608; }
    else if (i < 524288)  { s = s2; d = d2; off = i - 262144; }
    else if (i < 1572864) { s = s3; d = d3; off = i - 524288; }
    else                  { s = s4; d = d4; off = i - 1572864; }
    float4 v = ((const float4*)s)[off];
    v.x = tf32rf(v.x); v.y = tf32rf(v.y); v.z = tf32rf(v.z); v.w = tf32rf(v.w);
    ((float4*)d)[off] = v;
}

// ===========================================================================
// LayerNorm (output rounded to tf32-exact fp32; feeds GEMM A only)
// ===========================================================================
__global__ void ln_kernel(const float* __restrict__ X, const float* __restrict__ g,
                          const float* __restrict__ b, float* __restrict__ Y) {
    const int row = blockIdx.x;
    const int t = threadIdx.x;  // 128 threads
    const float4* Xv = (const float4*)(X + (size_t)row * EDIM);
    float4 v = Xv[t];

    __shared__ float red[4];
    float s = v.x + v.y + v.z + v.w;
    #pragma unroll
    for (int o = 16; o > 0; o >>= 1) s += __shfl_down_sync(0xffffffffu, s, o);
    if ((t & 31) == 0) red[t >> 5] = s;
    __syncthreads();
    float mean = (red[0] + red[1] + red[2] + red[3]) * (1.0f / EDIM);
    __syncthreads();

    float dx = v.x - mean, dy = v.y - mean, dz = v.z - mean, dw = v.w - mean;
    float s2 = dx * dx + dy * dy + dz * dz + dw * dw;
    #pragma unroll
    for (int o = 16; o > 0; o >>= 1) s2 += __shfl_down_sync(0xffffffffu, s2, o);
    if ((t & 31) == 0) red[t >> 5] = s2;
    __syncthreads();
    float var = (red[0] + red[1] + red[2] + red[3]) * (1.0f / EDIM);
    float rs = rsqrtf(var + 1e-5f);

    float4 gv = ((const float4*)g)[t];
    float4 bv = ((const float4*)b)[t];
    float4 o4;
    o4.x = tf32rf(dx * rs * gv.x + bv.x);
    o4.y = tf32rf(dy * rs * gv.y + bv.y);
    o4.z = tf32rf(dz * rs * gv.z + bv.z);
    o4.w = tf32rf(dw * rs * gv.w + bv.w);
    ((float4*)(Y + (size_t)row * EDIM))[t] = o4;
}

// ===========================================================================
// tf32 mma.sync GEMM: C[M,N] = A[M,K]*B[N,K]^T (+bias, +res, +relu, +round)
// CTA MTx128 (MT=128 or 64), 8 warps, warp tile (MT/2)x32, K-chunk 16.
// 3-stage cp.async pipeline (1 sync/chunk); ldmatrix.x4 fragment loads.
// Inputs tf32-exact fp32 -> raw-bit MMA feed exact (RNA at producers).
// ===========================================================================
#define SMS 20                  // smem row stride (uint32)

template <int MT, bool RELU, bool RES, bool ROUND>
__global__ void __launch_bounds__(256, 2)
mma_gemm(const float* __restrict__ A, const float* __restrict__ B,
         const float* __restrict__ bias, const float* __restrict__ Rs,
         float* __restrict__ C, int M, int N, int K) {
    constexpr int A_STAGE = MT * SMS;
    constexpr int B_STAGE = 128 * SMS;
    constexpr int MI = MT / 32;     // A fragments per warp
    constexpr int LA = MT / 64;     // A float4 loads per thread per chunk

    extern __shared__ uint32_t dsm[];
    uint32_t* sA = dsm;                    // 3 x A_STAGE
    uint32_t* sB = dsm + 3 * A_STAGE;      // 3 x B_STAGE

    const int t = threadIdx.x;
    const int wid = t >> 5;
    const int lid = t & 31;
    const int mBase = blockIdx.y * MT;
    const int nBase = blockIdx.x * 128;

    const int wm = (wid >> 2) * (MT / 2);
    const int wn = (wid & 3) * 32;
    const int g = lid >> 2;
    const int t4 = lid & 3;

    float acc[MI][4][4];
    #pragma unroll
    for (int mi = 0; mi < MI; mi++)
        #pragma unroll
        for (int ni = 0; ni < 4; ni++)
            #pragma unroll
            for (int r = 0; r < 4; r++) acc[mi][ni][r] = 0.0f;

    // cp.async loader indexing: A has MT*4 float4 slots/chunk, B has 512.
    const float* ApL[LA];
    uint32_t saL[3][LA];
    #pragma unroll
    for (int i = 0; i < LA; i++) {
        int s = t * LA + i;
        int row = s >> 2, q = (s & 3) * 4;
        ApL[i] = A + (size_t)(mBase + row) * K + q;
        #pragma unroll
        for (int st = 0; st < 3; st++)
            saL[st][i] = smem_u32(&sA[st * A_STAGE + row * SMS + q]);
    }
    const float* BpL[2];
    uint32_t sbL[3][2];
    #pragma unroll
    for (int i = 0; i < 2; i++) {
        int s = t * 2 + i;
        int row = s >> 2, q = (s & 3) * 4;
        BpL[i] = B + (size_t)(nBase + row) * K + q;
        #pragma unroll
        for (int st = 0; st < 3; st++)
            sbL[st][i] = smem_u32(&sB[st * B_STAGE + row * SMS + q]);
    }

    // ldmatrix per-lane base addresses (stage 0), uint32 elems
    const int a_elem = (wm + (lid & 15)) * SMS + ((lid >> 4) << 2);
    const int b_elem = (wn + ((lid >> 4) << 3) + (lid & 7)) * SMS + (((lid >> 3) & 1) << 2);
    uint32_t aB[3], bB[3];
    #pragma unroll
    for (int st = 0; st < 3; st++) {
        aB[st] = smem_u32(&sA[st * A_STAGE + a_elem]);
        bB[st] = smem_u32(&sB[st * B_STAGE + b_elem]);
    }

    auto issue_chunk = [&](int c, int st) {
        const int k0 = c << 4;
        #pragma unroll
        for (int i = 0; i < LA; i++) cpa16(saL[st][i], ApL[i] + k0);
        #pragma unroll
        for (int i = 0; i < 2; i++) cpa16(sbL[st][i], BpL[i] + k0);
    };

    const int T = K >> 4;
    issue_chunk(0, 0); CP_COMMIT();
    if (T > 1) { issue_chunk(1, 1); CP_COMMIT(); }

    int st = 0;
    for (int c = 0; c < T; c++) {
        if (c + 1 < T) CP_WAIT1(); else CP_WAIT0();
        __syncthreads();  // chunk c visible to all; all warps done with iter c-1
        if (c + 2 < T) { issue_chunk(c + 2, (st + 2 >= 3) ? st - 1 : st + 2); CP_COMMIT(); }

        const uint32_t aBs = aB[st];
        const uint32_t bBs = bB[st];
        #pragma unroll
        for (int ks = 0; ks < 16; ks += 8) {
            uint32_t af[MI][4], bfr[2][4];
            #pragma unroll
            for (int mi = 0; mi < MI; mi++)
                ldsm_x4(af[mi], aBs + (mi * 16 * SMS + ks) * 4);
            #pragma unroll
            for (int nb = 0; nb < 2; nb++)
                ldsm_x4(bfr[nb], bBs + (nb * 16 * SMS + ks) * 4);
            #pragma unroll
            for (int mi = 0; mi < MI; mi++)
                #pragma unroll
                for (int ni = 0; ni < 4; ni++)
                    mma1688(acc[mi][ni], af[mi], &bfr[ni >> 1][(ni & 1) * 2]);
        }
        st = (st + 1 == 3) ? 0 : st + 1;
        // no end-of-loop sync: next iteration's top sync provides the guard
    }

    // Epilogue
    #pragma unroll
    for (int mi = 0; mi < MI; mi++) {
        #pragma unroll
        for (int ni = 0; ni < 4; ni++) {
            const int cc = nBase + wn + ni * 8 + 2 * t4;
            const float b0 = bias[cc], b1 = bias[cc + 1];
            #pragma unroll
            for (int h = 0; h < 2; h++) {
                const int row = mBase + wm + mi * 16 + g + h * 8;
                float v0 = acc[mi][ni][2 * h + 0] + b0;
                float v1 = acc[mi][ni][2 * h + 1] + b1;
                if (RES) {
                    const float* rr = Rs + (size_t)row * N + cc;
                    v0 += rr[0]; v1 += rr[1];
                }
                if (RELU) { v0 = fmaxf(v0, 0.0f); v1 = fmaxf(v1, 0.0f); }
                if (ROUND) { v0 = tf32rf(v0); v1 = tf32rf(v1); }
                float2 o; o.x = v0; o.y = v1;
                *(float2*)(C + (size_t)row * N + cc) = o;
            }
        }
    }
}

static int gemm_smem(int mt) { return 3 * (mt + 128) * SMS * 4; }

// ===========================================================================
// Tensor-core flash attention (tf32 mma.sync); output rounded (feeds proj A)
// ===========================================================================
#define AQ_S 68
#define AV_S 72

__global__ void __launch_bounds__(128)
attn_mma_kernel(const float* __restrict__ qkv, float* __restrict__ out) {
    extern __shared__ uint32_t asmem[];
    uint32_t* Qs = asmem;                     // 128 x 68
    uint32_t* Ks = Qs + 128 * AQ_S;           // 64 x 68
    uint32_t* Vs = Ks + 64 * AQ_S;            // 64 x 72
    uint32_t* Ss = Vs + 64 * AV_S;            // 128 x 68
    float* rowM = (float*)(Ss + 128 * AQ_S);
    float* rowL = rowM + 128;
    float* rowA = rowL + 128;

    const int t = threadIdx.x;
    const int wid = t >> 5;
    const int lid = t & 31;
    const int g = lid >> 2, t4 = lid & 3;
    const int h = blockIdx.y;
    const int qb = blockIdx.x * 128;
    const int wrow = wid * 32;

    for (int i = t; i < 128 * 16; i += 128) {
        int r = i >> 4, d4 = (i & 15) * 4;
        float4 q = *(const float4*)(qkv + (size_t)(qb + r) * 1536 + h * 64 + d4);
        uint32_t* dst = &Qs[r * AQ_S + d4];
        dst[0] = tf32r(q.x * 0.125f); dst[1] = tf32r(q.y * 0.125f);
        dst[2] = tf32r(q.z * 0.125f); dst[3] = tf32r(q.w * 0.125f);
    }
    rowM[t] = -1e30f;
    rowL[t] = 0.0f;

    float o[2][8][4];
    #pragma unroll
    for (int mi = 0; mi < 2; mi++)
        #pragma unroll
        for (int ni = 0; ni < 8; ni++)
            #pragma unroll
            for (int r = 0; r < 4; r++) o[mi][ni][r] = 0.0f;

    for (int kb = 0; kb < NSEQ; kb += 64) {
        __syncthreads();
        for (int i = t; i < 64 * 16; i += 128) {
            int r = i >> 4, d4 = (i & 15) * 4;
            const float* base = qkv + (size_t)(kb + r) * 1536 + h * 64 + d4;
            float4 kv = *(const float4*)(base + 512);
            float4 vv = *(const float4*)(base + 1024);
            uint32_t* kd = &Ks[r * AQ_S + d4];
            kd[0] = tf32r(kv.x); kd[1] = tf32r(kv.y);
            kd[2] = tf32r(kv.z); kd[3] = tf32r(kv.w);
            uint32_t* vd = &Vs[r * AV_S + d4];
            vd[0] = tf32r(vv.x); vd[1] = tf32r(vv.y);
            vd[2] = tf32r(vv.z); vd[3] = tf32r(vv.w);
        }
        __syncthreads();

        float sf[2][8][4];
        #pragma unroll
        for (int mi = 0; mi < 2; mi++)
            #pragma unroll
            for (int ni = 0; ni < 8; ni++)
                #pragma unroll
                for (int r = 0; r < 4; r++) sf[mi][ni][r] = 0.0f;

        #pragma unroll
        for (int ks = 0; ks < 64; ks += 8) {
            uint32_t af[2][4];
            #pragma unroll
            for (int mi = 0; mi < 2; mi++) {
                int base = (wrow + mi * 16 + g) * AQ_S + ks + t4;
                af[mi][0] = Qs[base];
                af[mi][1] = Qs[base + 8 * AQ_S];
                af[mi][2] = Qs[base + 4];
                af[mi][3] = Qs[base + 8 * AQ_S + 4];
            }
            #pragma unroll
            for (int ni = 0; ni < 8; ni++) {
                uint32_t bf[2];
                int base = (ni * 8 + g) * AQ_S + ks + t4;
                bf[0] = Ks[base];
                bf[1] = Ks[base + 4];
                mma1688(sf[0][ni], af[0], bf);
                mma1688(sf[1][ni], af[1], bf);
            }
        }
        #pragma unroll
        for (int mi = 0; mi < 2; mi++) {
            #pragma unroll
            for (int ni = 0; ni < 8; ni++) {
                int r0 = wrow + mi * 16 + g;
                int cc = ni * 8 + 2 * t4;
                float2 lo; lo.x = sf[mi][ni][0]; lo.y = sf[mi][ni][1];
                float2 hi; hi.x = sf[mi][ni][2]; hi.y = sf[mi][ni][3];
                *(float2*)&((float*)Ss)[r0 * AQ_S + cc] = lo;
                *(float2*)&((float*)Ss)[(r0 + 8) * AQ_S + cc] = hi;
            }
        }
        __syncthreads();

        {
            float* Sr = (float*)Ss + t * AQ_S;
            uint32_t* Pr = Ss + t * AQ_S;
            float mprev = rowM[t];
            float mx = mprev;
            #pragma unroll 8
            for (int j = 0; j < 64; j++) mx = fmaxf(mx, Sr[j]);
            float al = __expf(mprev - mx);
            float sum = 0.0f;
            #pragma unroll 8
            for (int j = 0; j < 64; j++) {
                float p = __expf(Sr[j] - mx);
                sum += p;
                Pr[j] = tf32r(p);
            }
            rowL[t] = rowL[t] * al + sum;
            rowM[t] = mx;
            rowA[t] = al;
        }
        __syncthreads();

        #pragma unroll
        for (int mi = 0; mi < 2; mi++) {
            float a0 = rowA[wrow + mi * 16 + g];
            float a1 = rowA[wrow + mi * 16 + g + 8];
            #pragma unroll
            for (int ni = 0; ni < 8; ni++) {
                o[mi][ni][0] *= a0; o[mi][ni][1] *= a0;
                o[mi][ni][2] *= a1; o[mi][ni][3] *= a1;
            }
        }
        #pragma unroll
        for (int ks = 0; ks < 64; ks += 8) {
            uint32_t af[2][4];
            #pragma unroll
            for (int mi = 0; mi < 2; mi++) {
                int base = (wrow + mi * 16 + g) * AQ_S + ks + t4;
                af[mi][0] = Ss[base];
                af[mi][1] = Ss[base + 8 * AQ_S];
                af[mi][2] = Ss[base + 4];
                af[mi][3] = Ss[base + 8 * AQ_S + 4];
            }
            #pragma unroll
            for (int ni = 0; ni < 8; ni++) {
                uint32_t bf[2];
                bf[0] = Vs[(ks + t4) * AV_S + ni * 8 + g];
                bf[1] = Vs[(ks + t4 + 4) * AV_S + ni * 8 + g];
                mma1688(o[0][ni], af[0], bf);
                mma1688(o[1][ni], af[1], bf);
            }
        }
    }

    #pragma unroll
    for (int mi = 0; mi < 2; mi++) {
        float inv0 = 1.0f / rowL[wrow + mi * 16 + g];
        float inv1 = 1.0f / rowL[wrow + mi * 16 + g + 8];
        #pragma unroll
        for (int ni = 0; ni < 8; ni++) {
            int cc = h * 64 + ni * 8 + 2 * t4;
            int r0 = qb + wrow + mi * 16 + g;
            float2 lo; lo.x = tf32rf(o[mi][ni][0] * inv0); lo.y = tf32rf(o[mi][ni][1] * inv0);
            float2 hi; hi.x = tf32rf(o[mi][ni][2] * inv1); hi.y = tf32rf(o[mi][ni][3] * inv1);
            *(float2*)(out + (size_t)r0 * EDIM + cc) = lo;
            *(float2*)(out + (size_t)(r0 + 8) * EDIM + cc) = hi;
        }
    }
}

static const int ATTN_SMEM =
    (128 * AQ_S + 64 * AQ_S + 64 * AV_S + 128 * AQ_S) * 4 + 3 * 128 * 4;

extern "C" void kernel_launch(void* const* d_in, const int* in_sizes, int n_in,
                              void* d_out, int out_size) {
    const float* x      = (const float*)d_in[0];
    const float* ln_g   = (const float*)d_in[1];
    const float* ln_b   = (const float*)d_in[2];
    const float* qkv_w  = (const float*)d_in[3];
    const float* qkv_b  = (const float*)d_in[4];
    const float* proj_w = (const float*)d_in[5];
    const float* proj_b = (const float*)d_in[6];
    const float* fc1_w  = (const float*)d_in[7];
    const float* fc1_b  = (const float*)d_in[8];
    const float* fc2_w  = (const float*)d_in[9];
    const float* fc2_b  = (const float*)d_in[10];
    const float* fc3_w  = (const float*)d_in[11];
    const float* fc3_b  = (const float*)d_in[12];
    float* out = (float*)d_out;

    float *h1, *qkvb, *attnb, *x1, *h2, *m1, *m2;
    float *wqkv, *wproj, *w1, *w2, *w3;
    cudaGetSymbolAddress((void**)&h1, g_h1);
    cudaGetSymbolAddress((void**)&qkvb, g_qkv);
    cudaGetSymbolAddress((void**)&attnb, g_attn);
    cudaGetSymbolAddress((void**)&x1, g_x1);
    cudaGetSymbolAddress((void**)&h2, g_h2);
    cudaGetSymbolAddress((void**)&m1, g_m1);
    cudaGetSymbolAddress((void**)&m2, g_m2);
    cudaGetSymbolAddress((void**)&wqkv, g_wqkv);
    cudaGetSymbolAddress((void**)&wproj, g_wproj);
    cudaGetSymbolAddress((void**)&w1, g_w1);
    cudaGetSymbolAddress((void**)&w2, g_w2);
    cudaGetSymbolAddress((void**)&w3, g_w3);

    cudaFuncSetAttribute(attn_mma_kernel, cudaFuncAttributeMaxDynamicSharedMemorySize,
                         ATTN_SMEM);
    cudaFuncSetAttribute(mma_gemm<128, false, false, false>,
                         cudaFuncAttributeMaxDynamicSharedMemorySize, gemm_smem(128));
    cudaFuncSetAttribute(mma_gemm<64, false, true, false>,
                         cudaFuncAttributeMaxDynamicSharedMemorySize, gemm_smem(64));
    cudaFuncSetAttribute(mma_gemm<128, true, false, true>,
                         cudaFuncAttributeMaxDynamicSharedMemorySize, gemm_smem(128));

    // 0. Pre-round weights to tf32-exact fp32 (single fused kernel)
    round_w_all<<<7168, 256>>>(qkv_w, wqkv, proj_w, wproj, fc1_w, w1,
                               fc2_w, w2, fc3_w, w3);

    // 1. LN1 (rounded output)
    ln_kernel<<<NSEQ, 128>>>(x, ln_g, ln_b, h1);
    // 2. QKV: [4096,512] x [1536,512]^T
    mma_gemm<128, false, false, false><<<dim3(12, 32), 256, gemm_smem(128)>>>(
        h1, wqkv, qkv_b, nullptr, qkvb, NSEQ, 3 * EDIM, EDIM);
    // 3. Attention (rounded output)
    attn_mma_kernel<<<dim3(32, NHEAD), 128, ATTN_SMEM>>>(qkvb, attnb);
    // 4. proj + residual (64-row tiles -> 256 CTAs)
    mma_gemm<64, false, true, false><<<dim3(4, 64), 256, gemm_smem(64)>>>(
        attnb, wproj, proj_b, x, x1, NSEQ, EDIM, EDIM);
    // 5. LN2 (rounded output)
    ln_kernel<<<NSEQ, 128>>>(x1, ln_g, ln_b, h2);
    // 6. fc1 + relu (rounded output)
    mma_gemm<128, true, false, true><<<dim3(16, 32), 256, gemm_smem(128)>>>(
        h2, w1, fc1_b, nullptr, m1, NSEQ, HDIM, EDIM);
    // 7. fc2 + relu (rounded output)
    mma_gemm<128, true, false, true><<<dim3(16, 32), 256, gemm_smem(128)>>>(
        m1, w2, fc2_b, nullptr, m2, NSEQ, HDIM, HDIM);
    // 8. fc3 + bias + residual -> out (64-row tiles -> 256 CTAs)
    mma_gemm<64, false, true, false><<<dim3(4, 64), 256, gemm_smem(64)>>>(
        m2, w3, fc3_b, x1, out, NSEQ, EDIM, HDIM);
}